// round 3
// baseline (speedup 1.0000x reference)
#include <cuda_runtime.h>
#include <cuda_bf16.h>

// Problem: x[16,64,256,256] f32, W[2,64], b[2]
//   y = 1x1 conv (channel contraction) + b ; e = exp(y)
//   s = e0 + e1 ; boxsum = 3x3 replicate-padded sum of s
//   out[b,h,w] = e0 / boxsum
//
// Strategy: 2 kernels through 8 MiB __device__ scratch (L2-resident).
//   K1: channel contraction (DRAM-bound, 256 MiB read) -> e0, s
//   K2: vectorized 3x3 clamped box sum + divide (L2-bound)

#define B 16
#define C 64
#define H 256
#define Wd 256
#define HW (H * Wd)          // 65536
#define NPIX (B * HW)        // 1048576
#define NP4 (NPIX / 4)       // 262144

__device__ float g_e0[NPIX];
__device__ float g_s[NPIX];

__global__ __launch_bounds__(256) void conv_exp_kernel(
    const float* __restrict__ x,
    const float* __restrict__ Wc,
    const float* __restrict__ bias)
{
    __shared__ float ws[2 * C + 2];
    int tid = threadIdx.x;
    if (tid < 2 * C) ws[tid] = Wc[tid];
    if (tid < 2) ws[2 * C + tid] = bias[tid];
    __syncthreads();

    int p4 = blockIdx.x * 256 + tid;          // float4 pixel-group index
    int bidx = p4 >> 14;                      // HW/4 = 16384 groups per batch
    int g = p4 & 16383;                       // group within batch image

    // x as float4: offset (b*64 + c)*16384 + g
    const float4* xb = reinterpret_cast<const float4*>(x)
                     + (size_t)bidx * C * (HW / 4) + g;

    float4 a0 = make_float4(0.f, 0.f, 0.f, 0.f);
    float4 a1 = make_float4(0.f, 0.f, 0.f, 0.f);

#pragma unroll 8
    for (int c = 0; c < C; c++) {
        float4 v = xb[(size_t)c * (HW / 4)];
        float w0 = ws[c];
        float w1 = ws[C + c];
        a0.x = fmaf(v.x, w0, a0.x);
        a0.y = fmaf(v.y, w0, a0.y);
        a0.z = fmaf(v.z, w0, a0.z);
        a0.w = fmaf(v.w, w0, a0.w);
        a1.x = fmaf(v.x, w1, a1.x);
        a1.y = fmaf(v.y, w1, a1.y);
        a1.z = fmaf(v.z, w1, a1.z);
        a1.w = fmaf(v.w, w1, a1.w);
    }

    float b0 = ws[2 * C], b1 = ws[2 * C + 1];

    float4 e0, e1;
    e0.x = expf(a0.x + b0); e0.y = expf(a0.y + b0);
    e0.z = expf(a0.z + b0); e0.w = expf(a0.w + b0);
    e1.x = expf(a1.x + b1); e1.y = expf(a1.y + b1);
    e1.z = expf(a1.z + b1); e1.w = expf(a1.w + b1);

    float4 s;
    s.x = e0.x + e1.x; s.y = e0.y + e1.y;
    s.z = e0.z + e1.z; s.w = e0.w + e1.w;

    reinterpret_cast<float4*>(g_e0)[p4] = e0;
    reinterpret_cast<float4*>(g_s)[p4]  = s;
}

__global__ __launch_bounds__(256) void box_div_kernel(float* __restrict__ out)
{
    int p4 = blockIdx.x * 256 + threadIdx.x;
    int bidx = p4 >> 14;
    int hw = (p4 & 16383) << 2;               // first pixel of the group
    int h = hw >> 8;
    int w = hw & 255;

    const float* sb = g_s + bidx * HW;

    float4 acc = make_float4(0.f, 0.f, 0.f, 0.f);

#pragma unroll
    for (int dh = -1; dh <= 1; dh++) {
        int hh = h + dh;
        hh = hh < 0 ? 0 : (hh > 255 ? 255 : hh);
        const float* row = sb + hh * Wd;
        float4 v = *reinterpret_cast<const float4*>(row + w);
        float l = (w == 0)        ? v.x : row[w - 1];   // replicate pad
        float r = (w + 4 == Wd)   ? v.w : row[w + 4];
        acc.x += l   + v.x + v.y;
        acc.y += v.x + v.y + v.z;
        acc.z += v.y + v.z + v.w;
        acc.w += v.z + v.w + r;
    }

    float4 e = reinterpret_cast<const float4*>(g_e0)[p4];
    float4 o;
    o.x = e.x / acc.x;
    o.y = e.y / acc.y;
    o.z = e.z / acc.z;
    o.w = e.w / acc.w;
    reinterpret_cast<float4*>(out)[p4] = o;
}

extern "C" void kernel_launch(void* const* d_in, const int* in_sizes, int n_in,
                              void* d_out, int out_size)
{
    const float* x  = (const float*)d_in[0];
    const float* Wc = (const float*)d_in[1];
    const float* bs = (const float*)d_in[2];
    float* out = (float*)d_out;

    conv_exp_kernel<<<NP4 / 256, 256>>>(x, Wc, bs);
    box_div_kernel<<<NP4 / 256, 256>>>(out);
}

// round 8
// speedup vs baseline: 1.0255x; 1.0255x over previous
#include <cuda_runtime.h>
#include <cuda_bf16.h>

// x[16,64,256,256] f32, W[2,64], b[2]
//   e = exp(1x1conv(x) + b); s = e0+e1; out = e0 / boxsum3x3_replicate(s)
// K1: channel contraction, 2 float4 groups (8 px) per thread, __ldcs streaming
// K2: 3x3 clamped box + divide, 8 px per thread

#define B 16
#define C 64
#define H 256
#define Wd 256
#define HW (H * Wd)          // 65536
#define NPIX (B * HW)        // 1048576
#define NP4 (NPIX / 4)       // 262144
#define NP8 (NPIX / 8)       // 131072

__device__ float g_e0[NPIX];
__device__ float g_s[NPIX];

__global__ __launch_bounds__(256) void conv_exp_kernel(
    const float* __restrict__ x,
    const float* __restrict__ Wc,
    const float* __restrict__ bias)
{
    __shared__ float ws[2 * C + 2];
    int tid = threadIdx.x;
    if (tid < 2 * C) ws[tid] = Wc[tid];
    if (tid < 2) ws[2 * C + tid] = bias[tid];
    __syncthreads();

    int p8 = blockIdx.x * 256 + tid;          // 8-pixel group index
    int bidx = p8 >> 13;                      // 8192 groups of 8 px per image
    int gp = p8 & 8191;
    int g = gp * 2;                           // first float4 group in image

    const float4* xb = reinterpret_cast<const float4*>(x)
                     + (size_t)bidx * C * (HW / 4) + g;

    float4 a0lo = make_float4(0.f, 0.f, 0.f, 0.f);
    float4 a0hi = make_float4(0.f, 0.f, 0.f, 0.f);
    float4 a1lo = make_float4(0.f, 0.f, 0.f, 0.f);
    float4 a1hi = make_float4(0.f, 0.f, 0.f, 0.f);

#pragma unroll 8
    for (int c = 0; c < C; c++) {
        float4 va = __ldcs(xb + (size_t)c * (HW / 4));
        float4 vb = __ldcs(xb + (size_t)c * (HW / 4) + 1);
        float w0 = ws[c];
        float w1 = ws[C + c];
        a0lo.x = fmaf(va.x, w0, a0lo.x);
        a0lo.y = fmaf(va.y, w0, a0lo.y);
        a0lo.z = fmaf(va.z, w0, a0lo.z);
        a0lo.w = fmaf(va.w, w0, a0lo.w);
        a0hi.x = fmaf(vb.x, w0, a0hi.x);
        a0hi.y = fmaf(vb.y, w0, a0hi.y);
        a0hi.z = fmaf(vb.z, w0, a0hi.z);
        a0hi.w = fmaf(vb.w, w0, a0hi.w);
        a1lo.x = fmaf(va.x, w1, a1lo.x);
        a1lo.y = fmaf(va.y, w1, a1lo.y);
        a1lo.z = fmaf(va.z, w1, a1lo.z);
        a1lo.w = fmaf(va.w, w1, a1lo.w);
        a1hi.x = fmaf(vb.x, w1, a1hi.x);
        a1hi.y = fmaf(vb.y, w1, a1hi.y);
        a1hi.z = fmaf(vb.z, w1, a1hi.z);
        a1hi.w = fmaf(vb.w, w1, a1hi.w);
    }

    float b0 = ws[2 * C], b1 = ws[2 * C + 1];

    float4 e0a, e0b, sa, sb;
    e0a.x = __expf(a0lo.x + b0); e0a.y = __expf(a0lo.y + b0);
    e0a.z = __expf(a0lo.z + b0); e0a.w = __expf(a0lo.w + b0);
    e0b.x = __expf(a0hi.x + b0); e0b.y = __expf(a0hi.y + b0);
    e0b.z = __expf(a0hi.z + b0); e0b.w = __expf(a0hi.w + b0);

    sa.x = e0a.x + __expf(a1lo.x + b1);
    sa.y = e0a.y + __expf(a1lo.y + b1);
    sa.z = e0a.z + __expf(a1lo.z + b1);
    sa.w = e0a.w + __expf(a1lo.w + b1);
    sb.x = e0b.x + __expf(a1hi.x + b1);
    sb.y = e0b.y + __expf(a1hi.y + b1);
    sb.z = e0b.z + __expf(a1hi.z + b1);
    sb.w = e0b.w + __expf(a1hi.w + b1);

    float4* e0p = reinterpret_cast<float4*>(g_e0) + p8 * 2;
    float4* sp  = reinterpret_cast<float4*>(g_s)  + p8 * 2;
    e0p[0] = e0a; e0p[1] = e0b;
    sp[0]  = sa;  sp[1]  = sb;
}

__global__ __launch_bounds__(256) void box_div_kernel(float* __restrict__ out)
{
    int p8 = blockIdx.x * 256 + threadIdx.x;  // 8-pixel group
    int bidx = p8 >> 13;
    int hw = (p8 & 8191) << 3;                // first pixel
    int h = hw >> 8;
    int w = hw & 255;

    const float* sbase = g_s + bidx * HW;

    float4 acc0 = make_float4(0.f, 0.f, 0.f, 0.f);
    float4 acc1 = make_float4(0.f, 0.f, 0.f, 0.f);

#pragma unroll
    for (int dh = -1; dh <= 1; dh++) {
        int hh = h + dh;
        hh = hh < 0 ? 0 : (hh > 255 ? 255 : hh);
        const float* row = sbase + hh * Wd;
        float4 va = *reinterpret_cast<const float4*>(row + w);
        float4 vb = *reinterpret_cast<const float4*>(row + w + 4);
        float l = (w == 0)        ? va.x : row[w - 1];
        float r = (w + 8 == Wd)   ? vb.w : row[w + 8];
        acc0.x += l    + va.x + va.y;
        acc0.y += va.x + va.y + va.z;
        acc0.z += va.y + va.z + va.w;
        acc0.w += va.z + va.w + vb.x;
        acc1.x += va.w + vb.x + vb.y;
        acc1.y += vb.x + vb.y + vb.z;
        acc1.z += vb.y + vb.z + vb.w;
        acc1.w += vb.z + vb.w + r;
    }

    const float4* e0p = reinterpret_cast<const float4*>(g_e0) + p8 * 2;
    float4 ea = e0p[0];
    float4 eb = e0p[1];

    float4 oa, ob;
    oa.x = ea.x / acc0.x; oa.y = ea.y / acc0.y;
    oa.z = ea.z / acc0.z; oa.w = ea.w / acc0.w;
    ob.x = eb.x / acc1.x; ob.y = eb.y / acc1.y;
    ob.z = eb.z / acc1.z; ob.w = eb.w / acc1.w;

    float4* op = reinterpret_cast<float4*>(out) + p8 * 2;
    op[0] = oa;
    op[1] = ob;
}

extern "C" void kernel_launch(void* const* d_in, const int* in_sizes, int n_in,
                              void* d_out, int out_size)
{
    const float* x  = (const float*)d_in[0];
    const float* Wc = (const float*)d_in[1];
    const float* bs = (const float*)d_in[2];
    float* out = (float*)d_out;

    conv_exp_kernel<<<NP8 / 256, 256>>>(x, Wc, bs);
    box_div_kernel<<<NP8 / 256, 256>>>(out);
}

// round 13
// speedup vs baseline: 1.0846x; 1.0576x over previous
#include <cuda_runtime.h>
#include <cuda_bf16.h>

// x[16,64,256,256] f32, W[2,64], b[2]
//   e = exp(1x1conv(x) + b); s = e0+e1; out = e0 / boxsum3x3_replicate(s)
// K1: channel contraction, 4 float4 groups (16 px) per thread, __ldcs streaming.
//     256 blocks -> fully resident, no wave tail.
// K2: 3x3 clamped box + divide, 4 px/thread (best measured), __ldcs scratch reads,
//     reversed block order to hit the scratch K1 wrote last (still in L2).

#define B 16
#define C 64
#define H 256
#define Wd 256
#define HW (H * Wd)          // 65536
#define NPIX (B * HW)        // 1048576
#define NP4 (NPIX / 4)       // 262144
#define NP16 (NPIX / 16)     // 65536

__device__ float g_e0[NPIX];
__device__ float g_s[NPIX];

__global__ __launch_bounds__(256) void conv_exp_kernel(
    const float* __restrict__ x,
    const float* __restrict__ Wc,
    const float* __restrict__ bias)
{
    __shared__ float ws[2 * C + 2];
    int tid = threadIdx.x;
    if (tid < 2 * C) ws[tid] = Wc[tid];
    if (tid < 2) ws[2 * C + tid] = bias[tid];
    __syncthreads();

    int p16 = blockIdx.x * 256 + tid;         // 16-pixel group index
    int bidx = p16 >> 12;                     // 4096 groups of 16 px per image
    int g = (p16 & 4095) * 4;                 // first float4 group in image

    const float4* xb = reinterpret_cast<const float4*>(x)
                     + (size_t)bidx * C * (HW / 4) + g;

    float4 a0[4], a1[4];
#pragma unroll
    for (int k = 0; k < 4; k++) {
        a0[k] = make_float4(0.f, 0.f, 0.f, 0.f);
        a1[k] = make_float4(0.f, 0.f, 0.f, 0.f);
    }

#pragma unroll 4
    for (int c = 0; c < C; c++) {
        const float4* xc = xb + (size_t)c * (HW / 4);
        float4 v[4];
#pragma unroll
        for (int k = 0; k < 4; k++)
            v[k] = __ldcs(xc + k);
        float w0 = ws[c];
        float w1 = ws[C + c];
#pragma unroll
        for (int k = 0; k < 4; k++) {
            a0[k].x = fmaf(v[k].x, w0, a0[k].x);
            a0[k].y = fmaf(v[k].y, w0, a0[k].y);
            a0[k].z = fmaf(v[k].z, w0, a0[k].z);
            a0[k].w = fmaf(v[k].w, w0, a0[k].w);
            a1[k].x = fmaf(v[k].x, w1, a1[k].x);
            a1[k].y = fmaf(v[k].y, w1, a1[k].y);
            a1[k].z = fmaf(v[k].z, w1, a1[k].z);
            a1[k].w = fmaf(v[k].w, w1, a1[k].w);
        }
    }

    float b0 = ws[2 * C], b1 = ws[2 * C + 1];

    float4* e0p = reinterpret_cast<float4*>(g_e0) + p16 * 4;
    float4* sp  = reinterpret_cast<float4*>(g_s)  + p16 * 4;

#pragma unroll
    for (int k = 0; k < 4; k++) {
        float4 e0, s;
        e0.x = __expf(a0[k].x + b0);
        e0.y = __expf(a0[k].y + b0);
        e0.z = __expf(a0[k].z + b0);
        e0.w = __expf(a0[k].w + b0);
        s.x = e0.x + __expf(a1[k].x + b1);
        s.y = e0.y + __expf(a1[k].y + b1);
        s.z = e0.z + __expf(a1[k].z + b1);
        s.w = e0.w + __expf(a1[k].w + b1);
        e0p[k] = e0;
        sp[k]  = s;
    }
}

__global__ __launch_bounds__(256) void box_div_kernel(float* __restrict__ out)
{
    // Reversed block order: consume the scratch K1 wrote LAST first (L2-hot).
    int rb = gridDim.x - 1 - blockIdx.x;
    int p4 = rb * 256 + threadIdx.x;
    int bidx = p4 >> 14;
    int hw = (p4 & 16383) << 2;               // first pixel of the group
    int h = hw >> 8;
    int w = hw & 255;

    const float* sb = g_s + bidx * HW;

    float4 acc = make_float4(0.f, 0.f, 0.f, 0.f);

#pragma unroll
    for (int dh = -1; dh <= 1; dh++) {
        int hh = h + dh;
        hh = hh < 0 ? 0 : (hh > 255 ? 255 : hh);
        const float* row = sb + hh * Wd;
        float4 v = __ldcs(reinterpret_cast<const float4*>(row + w));
        float l = (w == 0)        ? v.x : __ldcs(row + w - 1);  // replicate pad
        float r = (w + 4 == Wd)   ? v.w : __ldcs(row + w + 4);
        acc.x += l   + v.x + v.y;
        acc.y += v.x + v.y + v.z;
        acc.z += v.y + v.z + v.w;
        acc.w += v.z + v.w + r;
    }

    float4 e = __ldcs(reinterpret_cast<const float4*>(g_e0) + p4);
    float4 o;
    o.x = e.x / acc.x;
    o.y = e.y / acc.y;
    o.z = e.z / acc.z;
    o.w = e.w / acc.w;
    reinterpret_cast<float4*>(out)[p4] = o;
}

extern "C" void kernel_launch(void* const* d_in, const int* in_sizes, int n_in,
                              void* d_out, int out_size)
{
    const float* x  = (const float*)d_in[0];
    const float* Wc = (const float*)d_in[1];
    const float* bs = (const float*)d_in[2];
    float* out = (float*)d_out;

    conv_exp_kernel<<<NP16 / 256, 256>>>(x, Wc, bs);
    box_div_kernel<<<NP4 / 256, 256>>>(out);
}